// round 1
// baseline (speedup 1.0000x reference)
#include <cuda_runtime.h>

#define NSAMPLE 32
#define MAXN 4096

// scratch (no allocation allowed)
__device__ int g_cnt[MAXN];
__device__ int g_off[MAXN];
__device__ int g_ball[MAXN * NSAMPLE];

// ---------------------------------------------------------------------------
// Pass 0: zero the whole output buffer (poisoned by harness; tail must be 0)
// ---------------------------------------------------------------------------
__global__ void zero_kernel(float4* __restrict__ out, int n4, float* __restrict__ tail, int ntail) {
    int idx = blockIdx.x * blockDim.x + threadIdx.x;
    int stride = gridDim.x * blockDim.x;
    float4 z = make_float4(0.f, 0.f, 0.f, 0.f);
    for (int i = idx; i < n4; i += stride) out[i] = z;
    if (idx < ntail) tail[idx] = 0.f;
}

// ---------------------------------------------------------------------------
// Pass 1: warp-per-point ball query with RoI pruning, ordered first-32 select
// ---------------------------------------------------------------------------
__global__ void query_kernel(const float* __restrict__ xyz,
                             const float* __restrict__ new_xyz,
                             const float* __restrict__ rois,
                             int N, int Nb, int M, int K) {
    int warp = (blockIdx.x * blockDim.x + threadIdx.x) >> 5;
    int lane = threadIdx.x & 31;
    if (warp >= N) return;
    int i = warp;

    float px = xyz[3 * i + 0];
    float py = xyz[3 * i + 1];
    float pz = xyz[3 * i + 2];
    int b = i / Nb;
    int MK = M * K;
    const float* roib  = rois    + (size_t)b * M * 7;
    const float* gridb = new_xyz + (size_t)b * MK * 3;

    int cnt = 0;
    int ngroups = (M + 31) >> 5;
    for (int g = 0; g < ngroups && cnt < NSAMPLE; ++g) {
        int r = (g << 5) + lane;
        bool ib = false;
        if (r < M) {
            const float* ro = roib + (size_t)r * 7;
            float dx = px - ro[0], dy = py - ro[1], dz = pz - ro[2];
            // exact left-to-right, no FMA contraction (match reference compare)
            float d2b = __fadd_rn(__fadd_rn(__fmul_rn(dx, dx), __fmul_rn(dy, dy)), __fmul_rn(dz, dz));
            float r2  = __fadd_rn(__fadd_rn(__fmul_rn(ro[3], ro[3]), __fmul_rn(ro[4], ro[4])), __fmul_rn(ro[5], ro[5]));
            ib = (d2b <= r2);
        }
        unsigned rm = __ballot_sync(0xffffffffu, ib);
        while (rm && cnt < NSAMPLE) {
            int rb = __ffs(rm) - 1;
            rm &= rm - 1;
            int roi = (g << 5) + rb;
            int basej = roi * K;
            int nchunks = (K + 31) >> 5;
            for (int c = 0; c < nchunks && cnt < NSAMPLE; ++c) {
                int jl = (c << 5) + lane;
                int j = basej + jl;
                bool ok = false;
                if (jl < K) {
                    const float* gp = gridb + (size_t)j * 3;
                    float dx = px - gp[0], dy = py - gp[1], dz = pz - gp[2];
                    float d2 = __fadd_rn(__fadd_rn(__fmul_rn(dx, dx), __fmul_rn(dy, dy)), __fmul_rn(dz, dz));
                    ok = (d2 <= 1.0f);  // RADIUS^2
                }
                unsigned m = __ballot_sync(0xffffffffu, ok);
                int rank = cnt + __popc(m & ((1u << lane) - 1u));
                if (ok && rank < NSAMPLE)
                    g_ball[i * NSAMPLE + rank] = b * MK + j;
                cnt += __popc(m);
            }
        }
    }
    if (lane == 0) g_cnt[i] = cnt < NSAMPLE ? cnt : NSAMPLE;
}

// ---------------------------------------------------------------------------
// Pass 2: single-block exclusive scan of per-point counts
// ---------------------------------------------------------------------------
__global__ void scan_kernel(int N) {
    __shared__ int sh[1024];
    const int IT = (MAXN + 1023) / 1024;  // 4
    int t = threadIdx.x;
    int vals[IT];
    int tot = 0;
#pragma unroll
    for (int k = 0; k < IT; ++k) {
        int idx = t * IT + k;
        int v = (idx < N) ? g_cnt[idx] : 0;
        vals[k] = v;
        tot += v;
    }
    sh[t] = tot;
    __syncthreads();
    int v = tot;
    for (int off = 1; off < 1024; off <<= 1) {
        int y = (t >= off) ? sh[t - off] : 0;
        __syncthreads();
        v += y;
        sh[t] = v;
        __syncthreads();
    }
    int run = v - tot;  // exclusive prefix
#pragma unroll
    for (int k = 0; k < IT; ++k) {
        int idx = t * IT + k;
        if (idx < N) g_off[idx] = run;
        run += vals[k];
    }
}

// ---------------------------------------------------------------------------
// Pass 3: warp-per-point scatter of [xyz - grid, features] rows + indices
// ---------------------------------------------------------------------------
__global__ void scatter_kernel(const float* __restrict__ xyz,
                               const float* __restrict__ new_xyz_flat,
                               const float* __restrict__ feat,
                               float* __restrict__ out_gf,
                               float* __restrict__ out_idx,
                               int N, int C) {
    int warp = (blockIdx.x * blockDim.x + threadIdx.x) >> 5;
    int lane = threadIdx.x & 31;
    if (warp >= N) return;
    int i = warp;
    int D = 3 + C;

    float f = (lane < C) ? feat[(size_t)i * C + lane] : 0.f;
    float px = xyz[3 * i + 0];
    float py = xyz[3 * i + 1];
    float pz = xyz[3 * i + 2];
    float pme = (lane == 0) ? px : (lane == 1 ? py : pz);

    int cnt = g_cnt[i];
    int off = g_off[i];
    for (int s = 0; s < cnt; ++s) {
        int idx = g_ball[i * NSAMPLE + s];
        int pos = off + s;
        float* row = out_gf + (size_t)pos * D;
        if (lane < 3) {
            float gv = new_xyz_flat[(size_t)idx * 3 + lane];
            row[lane] = pme - gv;
        }
        if (lane < C) row[3 + lane] = f;
        if (lane == 0) out_idx[pos] = (float)idx;
    }
}

// ---------------------------------------------------------------------------
extern "C" void kernel_launch(void* const* d_in, const int* in_sizes, int n_in,
                              void* d_out, int out_size) {
    const float* xyz     = (const float*)d_in[0];
    // d_in[1] = xyz_batch_cnt (int32), only its length B is needed
    const float* new_xyz = (const float*)d_in[2];
    const float* rois    = (const float*)d_in[3];
    const float* feats   = (const float*)d_in[4];

    int N  = in_sizes[0] / 3;
    int B  = in_sizes[1];
    int Nb = N / B;
    int M  = in_sizes[3] / (B * 7);
    int K  = in_sizes[2] / (B * M * 3);
    int C  = in_sizes[4] / N;
    int L  = N * NSAMPLE;
    int D  = 3 + C;

    // Pass 0: zero full output
    int n4 = out_size / 4;
    int ntail = out_size - n4 * 4;
    zero_kernel<<<1024, 256>>>((float4*)d_out, n4, (float*)d_out + (size_t)n4 * 4, ntail);

    // Pass 1: ball query
    int nthreads = N * 32;
    query_kernel<<<(nthreads + 255) / 256, 256>>>(xyz, new_xyz, rois, N, Nb, M, K);

    // Pass 2: scan
    scan_kernel<<<1, 1024>>>(N);

    // Pass 3: scatter
    scatter_kernel<<<(nthreads + 255) / 256, 256>>>(
        xyz, new_xyz, feats,
        (float*)d_out, (float*)d_out + (size_t)L * D, N, C);
}